// round 1
// baseline (speedup 1.0000x reference)
#include <cuda_runtime.h>

#define NB 4
#define NS 8192
#define ND 512
#define NP 32
#define NT (NP + NS)          // 8224
#define LN_EPS 1e-5f
#define SCHUNKS 64
#define CHUNK (NS / SCHUNKS)  // 128

// Scratch (device globals — no allocation allowed in kernel_launch)
__device__ float g_part[SCHUNKS][NB * ND];  // per-S-chunk partial sums of x
__device__ float g_y[NB * ND];              // final per-batch output row

// ---------------------------------------------------------------------------
// Kernel 1: reduce x[b, s, d] over s into SCHUNKS deterministic partials.
// grid = (2, NB, SCHUNKS), block = 256. Thread handles one (b, d), 128 rows.
// ---------------------------------------------------------------------------
__global__ void reduce_x_kernel(const float* __restrict__ x) {
    const int d = blockIdx.x * 256 + threadIdx.x;  // 0..511
    const int b = blockIdx.y;
    const int z = blockIdx.z;
    const float* p = x + ((size_t)b * NS + (size_t)z * CHUNK) * ND + d;
    float a0 = 0.f, a1 = 0.f, a2 = 0.f, a3 = 0.f;
#pragma unroll
    for (int i = 0; i < CHUNK; i += 4) {
        a0 += p[(size_t)(i + 0) * ND];
        a1 += p[(size_t)(i + 1) * ND];
        a2 += p[(size_t)(i + 2) * ND];
        a3 += p[(size_t)(i + 3) * ND];
    }
    g_part[z][b * ND + d] = (a0 + a1) + (a2 + a3);
}

// ---------------------------------------------------------------------------
// Kernel 2: per-batch head. grid = NB blocks, 512 threads (one per d).
//   cbar = (sum_chunks + sum_p pm) / T
//   vbar = cbar @ Wv + bv
//   normed = LayerNorm(vbar) * gamma + beta
//   y     = normed @ Wout + bout
// ---------------------------------------------------------------------------
__global__ void head_kernel(const float* __restrict__ pm,
                            const float* __restrict__ Wv,
                            const float* __restrict__ bv,
                            const float* __restrict__ gamma,
                            const float* __restrict__ beta,
                            const float* __restrict__ Wout,
                            const float* __restrict__ bout) {
    const int b = blockIdx.x;
    const int d = threadIdx.x;  // 0..511
    __shared__ float sh[ND];
    __shared__ float red[ND];

    // cbar
    float a = 0.f;
#pragma unroll 8
    for (int z = 0; z < SCHUNKS; z++) a += g_part[z][b * ND + d];
#pragma unroll
    for (int p = 0; p < NP; p++) a += pm[p * ND + d];
    const float cb = a / (float)NT;
    sh[d] = cb;
    __syncthreads();

    // vbar[d] = sum_k cbar[k] * Wv[k, d] + bv[d]
    float vb = bv[d];
#pragma unroll 8
    for (int k = 0; k < ND; k++) vb += sh[k] * Wv[(size_t)k * ND + d];

    // mean over d
    red[d] = vb;
    __syncthreads();
    for (int s = ND / 2; s > 0; s >>= 1) {
        if (d < s) red[d] += red[d + s];
        __syncthreads();
    }
    const float mu = red[0] / (float)ND;
    __syncthreads();

    // variance over d
    const float diff = vb - mu;
    red[d] = diff * diff;
    __syncthreads();
    for (int s = ND / 2; s > 0; s >>= 1) {
        if (d < s) red[d] += red[d + s];
        __syncthreads();
    }
    const float var = red[0] / (float)ND;
    const float inv = 1.0f / sqrtf(var + LN_EPS);
    __syncthreads();

    // normed, then output projection
    const float nrm = diff * inv * gamma[d] + beta[d];
    sh[d] = nrm;
    __syncthreads();

    float y = bout[d];
#pragma unroll 8
    for (int k = 0; k < ND; k++) y += sh[k] * Wout[(size_t)k * ND + d];
    g_y[b * ND + d] = y;
}

// ---------------------------------------------------------------------------
// Kernel 3: broadcast y[b, :] into out[b, t, :] for all T rows.
// grid = (GX, NB), block = 256. float4 stores, write-bound.
// ---------------------------------------------------------------------------
__global__ void bcast_kernel(float* __restrict__ out) {
    const int b = blockIdx.y;
    const int tid = threadIdx.x;
    __shared__ float4 sy[ND / 4];  // 128 float4 = one output row
    if (tid < ND / 4) sy[tid] = ((const float4*)g_y)[b * (ND / 4) + tid];
    __syncthreads();

    float4* o = (float4*)out + (size_t)b * NT * (ND / 4);
    const size_t n4 = (size_t)NT * (ND / 4);  // 1,052,672 float4 per batch
    const size_t stride = (size_t)gridDim.x * blockDim.x;
    for (size_t i = (size_t)blockIdx.x * blockDim.x + tid; i < n4; i += stride)
        o[i] = sy[i & (ND / 4 - 1)];
}

// ---------------------------------------------------------------------------
extern "C" void kernel_launch(void* const* d_in, const int* in_sizes, int n_in,
                              void* d_out, int out_size) {
    const float* x     = (const float*)d_in[0];
    const float* pm    = (const float*)d_in[1];
    // d_in[2]=Wk, d_in[3]=bk, d_in[6]=Wq, d_in[7]=bq unused (math collapses)
    const float* Wv    = (const float*)d_in[4];
    const float* bv    = (const float*)d_in[5];
    const float* gamma = (const float*)d_in[8];
    const float* beta  = (const float*)d_in[9];
    const float* Wout  = (const float*)d_in[10];
    const float* bout  = (const float*)d_in[11];

    reduce_x_kernel<<<dim3(2, NB, SCHUNKS), 256>>>(x);
    head_kernel<<<NB, ND>>>(pm, Wv, bv, gamma, beta, Wout, bout);
    bcast_kernel<<<dim3(148, NB), 256>>>((float*)d_out);
}

// round 3
// speedup vs baseline: 2.8091x; 2.8091x over previous
#include <cuda_runtime.h>

#define NB 4
#define NS 8192
#define ND 512
#define NP 32
#define NT (NP + NS)          // 8224
#define LN_EPS 1e-5f
#define ZCH 128               // chunks over S for reduce
#define CROWS (NS / ZCH)      // 64 rows per chunk
#define KZ 8                  // split-K factor for GEMVs
#define KS (ND / KZ)          // 64 k per split

// Scratch: device globals, referenced ONLY from device code (host-side symbol
// addresses are host shadows — passing them as kernel args is the round-2 bug).
__device__ float g_part[ZCH][NB * ND];   // per-chunk partial sums of x
__device__ float g_vp[KZ][NB * ND];      // split-K partials of vbar
__device__ float g_yp[KZ][NB * ND];      // split-K partials of y

// ---------------------------------------------------------------------------
// K1: reduce x over S. grid (NB, ZCH), block 128. float4 loads, 64 rows/thr.
// ---------------------------------------------------------------------------
__global__ void reduce_x_kernel(const float4* __restrict__ x4) {
    const int d4 = threadIdx.x;            // 0..127
    const int b  = blockIdx.x;
    const int z  = blockIdx.y;
    const float4* p = x4 + ((size_t)(b * NS + z * CROWS)) * (ND / 4) + d4;
    float4 a0 = {0,0,0,0}, a1 = {0,0,0,0}, a2 = {0,0,0,0}, a3 = {0,0,0,0};
#pragma unroll
    for (int i = 0; i < CROWS; i += 4) {
        float4 v0 = p[(size_t)(i + 0) * (ND / 4)];
        float4 v1 = p[(size_t)(i + 1) * (ND / 4)];
        float4 v2 = p[(size_t)(i + 2) * (ND / 4)];
        float4 v3 = p[(size_t)(i + 3) * (ND / 4)];
        a0.x += v0.x; a0.y += v0.y; a0.z += v0.z; a0.w += v0.w;
        a1.x += v1.x; a1.y += v1.y; a1.z += v1.z; a1.w += v1.w;
        a2.x += v2.x; a2.y += v2.y; a2.z += v2.z; a2.w += v2.w;
        a3.x += v3.x; a3.y += v3.y; a3.z += v3.z; a3.w += v3.w;
    }
    float4 r;
    r.x = (a0.x + a1.x) + (a2.x + a3.x);
    r.y = (a0.y + a1.y) + (a2.y + a3.y);
    r.z = (a0.z + a1.z) + (a2.z + a3.z);
    r.w = (a0.w + a1.w) + (a2.w + a3.w);
    ((float4*)g_part[z])[b * (ND / 4) + d4] = r;
}

// ---------------------------------------------------------------------------
// K2: fused cbar + split-K GEMV1 (vbar partials).
// grid (NB, KZ), block 512. Block (b,z): slice k in [z*KS, (z+1)*KS).
// ---------------------------------------------------------------------------
__global__ void gemv1_kernel(const float* __restrict__ pm,
                             const float* __restrict__ Wv) {
    const int b = blockIdx.x, z = blockIdx.y, d = threadIdx.x;
    __shared__ float sk[KS];
    if (d < KS) {
        const int kk = z * KS + d;
        float a = 0.f;
#pragma unroll 16
        for (int c = 0; c < ZCH; c++) a += g_part[c][b * ND + kk];
#pragma unroll
        for (int p = 0; p < NP; p++) a += pm[p * ND + kk];
        sk[d] = a / (float)NT;
    }
    __syncthreads();
    const float* w = Wv + (size_t)(z * KS) * ND + d;
    float acc = 0.f;
#pragma unroll
    for (int k = 0; k < KS; k++) acc += sk[k] * w[(size_t)k * ND];
    g_vp[z][b * ND + d] = acc;
}

// ---------------------------------------------------------------------------
// K3: fused vbar-combine + LayerNorm + split-K GEMV2 (y partials).
// grid (NB, KZ), block 512. LN stats recomputed redundantly per block
// (identical deterministic order in every block).
// ---------------------------------------------------------------------------
__global__ void gemv2_kernel(const float* __restrict__ bv,
                             const float* __restrict__ gamma,
                             const float* __restrict__ beta,
                             const float* __restrict__ Wout) {
    const int b = blockIdx.x, z = blockIdx.y, d = threadIdx.x;
    __shared__ float red[ND];
    __shared__ float snorm[KS];

    float vb = bv[d];
#pragma unroll
    for (int c = 0; c < KZ; c++) vb += g_vp[c][b * ND + d];

    red[d] = vb;
    __syncthreads();
    for (int s = ND / 2; s > 0; s >>= 1) {
        if (d < s) red[d] += red[d + s];
        __syncthreads();
    }
    const float mu = red[0] / (float)ND;
    __syncthreads();
    const float diff = vb - mu;
    red[d] = diff * diff;
    __syncthreads();
    for (int s = ND / 2; s > 0; s >>= 1) {
        if (d < s) red[d] += red[d + s];
        __syncthreads();
    }
    const float inv = rsqrtf(red[0] / (float)ND + LN_EPS);
    const float nrm = diff * inv * gamma[d] + beta[d];
    if (d >= z * KS && d < (z + 1) * KS) snorm[d - z * KS] = nrm;
    __syncthreads();

    const float* w = Wout + (size_t)(z * KS) * ND + d;
    float acc = 0.f;
#pragma unroll
    for (int k = 0; k < KS; k++) acc += snorm[k] * w[(size_t)k * ND];
    g_yp[z][b * ND + d] = acc;
}

// ---------------------------------------------------------------------------
// K4: combine y partials + bout, broadcast row to all T positions.
// grid (148, NB), block 256. Write-bound.
// ---------------------------------------------------------------------------
__global__ void bcast_kernel(const float4* __restrict__ bout4,
                             float* __restrict__ out) {
    const int b = blockIdx.y;
    const int tid = threadIdx.x;
    __shared__ float4 sy[ND / 4];
    if (tid < ND / 4) {
        float4 a = bout4[tid];
#pragma unroll
        for (int z = 0; z < KZ; z++) {
            float4 v = ((const float4*)g_yp[z])[b * (ND / 4) + tid];
            a.x += v.x; a.y += v.y; a.z += v.z; a.w += v.w;
        }
        sy[tid] = a;
    }
    __syncthreads();

    float4* o = (float4*)out + (size_t)b * NT * (ND / 4);
    const size_t n4 = (size_t)NT * (ND / 4);
    const size_t stride = (size_t)gridDim.x * blockDim.x;
    for (size_t i = (size_t)blockIdx.x * blockDim.x + tid; i < n4; i += stride)
        o[i] = sy[i & (ND / 4 - 1)];
}

// ---------------------------------------------------------------------------
extern "C" void kernel_launch(void* const* d_in, const int* in_sizes, int n_in,
                              void* d_out, int out_size) {
    const float* x     = (const float*)d_in[0];
    const float* pm    = (const float*)d_in[1];
    // d_in[2]=Wk, [3]=bk, [6]=Wq, [7]=bq unused: softmax over zero-state and
    // constant-in-m logits collapse to uniform weights (see derivation).
    const float* Wv    = (const float*)d_in[4];
    const float* bv    = (const float*)d_in[5];
    const float* gamma = (const float*)d_in[8];
    const float* beta  = (const float*)d_in[9];
    const float* Wout  = (const float*)d_in[10];
    const float* bout  = (const float*)d_in[11];

    reduce_x_kernel<<<dim3(NB, ZCH), 128>>>((const float4*)x);
    gemv1_kernel<<<dim3(NB, KZ), ND>>>(pm, Wv);
    gemv2_kernel<<<dim3(NB, KZ), ND>>>(bv, gamma, beta, Wout);
    bcast_kernel<<<dim3(148, NB), 256>>>((const float4*)bout, (float*)d_out);
}

// round 4
// speedup vs baseline: 3.0302x; 1.0787x over previous
#include <cuda_runtime.h>

#define NB 4
#define NS 8192
#define ND 512
#define NP 32
#define NT (NP + NS)          // 8224
#define LN_EPS 1e-5f
#define ZCH 128               // chunks over S for reduce
#define CROWS (NS / ZCH)      // 64 rows per chunk
#define KZ 8                  // split-K factor for GEMVs
#define KS (ND / KZ)          // 64 k per split

// Scratch: device globals, referenced ONLY from device code.
__device__ float g_part[ZCH][NB * ND];   // per-chunk partial sums of x
__device__ float g_vp[KZ][NB * ND];      // split-K partials of vbar
__device__ float g_yp[KZ][NB * ND];      // split-K partials of y

// ---------------------------------------------------------------------------
// K1: reduce x over S. grid (NB, ZCH), block 128. float4 loads, 64 rows/thr,
// 8 independent accumulators for MLP depth 8.
// ---------------------------------------------------------------------------
__global__ void reduce_x_kernel(const float4* __restrict__ x4) {
    const int d4 = threadIdx.x;            // 0..127
    const int b  = blockIdx.x;
    const int z  = blockIdx.y;
    const float4* p = x4 + ((size_t)(b * NS + z * CROWS)) * (ND / 4) + d4;
    float4 a[8];
#pragma unroll
    for (int j = 0; j < 8; j++) a[j] = make_float4(0.f, 0.f, 0.f, 0.f);
#pragma unroll
    for (int i = 0; i < CROWS; i += 8) {
#pragma unroll
        for (int j = 0; j < 8; j++) {
            float4 v = p[(size_t)(i + j) * (ND / 4)];
            a[j].x += v.x; a[j].y += v.y; a[j].z += v.z; a[j].w += v.w;
        }
    }
    float4 r;
    r.x = ((a[0].x + a[1].x) + (a[2].x + a[3].x)) + ((a[4].x + a[5].x) + (a[6].x + a[7].x));
    r.y = ((a[0].y + a[1].y) + (a[2].y + a[3].y)) + ((a[4].y + a[5].y) + (a[6].y + a[7].y));
    r.z = ((a[0].z + a[1].z) + (a[2].z + a[3].z)) + ((a[4].z + a[5].z) + (a[6].z + a[7].z));
    r.w = ((a[0].w + a[1].w) + (a[2].w + a[3].w)) + ((a[4].w + a[5].w) + (a[6].w + a[7].w));
    ((float4*)g_part[z])[b * (ND / 4) + d4] = r;
}

// ---------------------------------------------------------------------------
// K2: fused cbar + split-K GEMV1 (vbar partials). grid (NB, KZ), block 512.
// ---------------------------------------------------------------------------
__global__ void gemv1_kernel(const float* __restrict__ pm,
                             const float* __restrict__ Wv) {
    const int b = blockIdx.x, z = blockIdx.y, d = threadIdx.x;
    __shared__ float sk[KS];
    if (d < KS) {
        const int kk = z * KS + d;
        float a = 0.f;
#pragma unroll 16
        for (int c = 0; c < ZCH; c++) a += g_part[c][b * ND + kk];
#pragma unroll
        for (int p = 0; p < NP; p++) a += pm[p * ND + kk];
        sk[d] = a / (float)NT;
    }
    __syncthreads();
    const float* w = Wv + (size_t)(z * KS) * ND + d;
    float acc = 0.f;
#pragma unroll
    for (int k = 0; k < KS; k++) acc += sk[k] * w[(size_t)k * ND];
    g_vp[z][b * ND + d] = acc;
}

// ---------------------------------------------------------------------------
// K3: fused vbar-combine + LayerNorm + split-K GEMV2 (y partials).
// grid (NB, KZ), block 512. LN stats recomputed redundantly per block
// (identical deterministic order in every block).
// ---------------------------------------------------------------------------
__global__ void gemv2_kernel(const float* __restrict__ bv,
                             const float* __restrict__ gamma,
                             const float* __restrict__ beta,
                             const float* __restrict__ Wout) {
    const int b = blockIdx.x, z = blockIdx.y, d = threadIdx.x;
    __shared__ float red[ND];
    __shared__ float snorm[KS];

    float vb = bv[d];
#pragma unroll
    for (int c = 0; c < KZ; c++) vb += g_vp[c][b * ND + d];

    red[d] = vb;
    __syncthreads();
    for (int s = ND / 2; s > 0; s >>= 1) {
        if (d < s) red[d] += red[d + s];
        __syncthreads();
    }
    const float mu = red[0] / (float)ND;
    __syncthreads();
    const float diff = vb - mu;
    red[d] = diff * diff;
    __syncthreads();
    for (int s = ND / 2; s > 0; s >>= 1) {
        if (d < s) red[d] += red[d + s];
        __syncthreads();
    }
    const float inv = rsqrtf(red[0] / (float)ND + LN_EPS);
    const float nrm = diff * inv * gamma[d] + beta[d];
    if (d >= z * KS && d < (z + 1) * KS) snorm[d - z * KS] = nrm;
    __syncthreads();

    const float* w = Wout + (size_t)(z * KS) * ND + d;
    float acc = 0.f;
#pragma unroll
    for (int k = 0; k < KS; k++) acc += snorm[k] * w[(size_t)k * ND];
    g_yp[z][b * ND + d] = acc;
}

// ---------------------------------------------------------------------------
// K4: combine y partials + bout, broadcast row to all T positions.
// grid (296, NB), block 256. Each thread's output float4 index mod 128 is
// CONSTANT (stride = 296*256 = 75776, multiple of 128), so the row value is
// loaded into a register ONCE; the loop is pure STG.128.
// ---------------------------------------------------------------------------
#define BGX 296
__global__ void bcast_kernel(const float4* __restrict__ bout4,
                             float* __restrict__ out) {
    const int b = blockIdx.y;
    const int tid = threadIdx.x;
    __shared__ float4 sy[ND / 4];
    if (tid < ND / 4) {
        float4 a = bout4[tid];
#pragma unroll
        for (int z = 0; z < KZ; z++) {
            float4 v = ((const float4*)g_yp[z])[b * (ND / 4) + tid];
            a.x += v.x; a.y += v.y; a.z += v.z; a.w += v.w;
        }
        sy[tid] = a;
    }
    __syncthreads();

    const size_t start  = (size_t)blockIdx.x * blockDim.x + tid;
    const float4 val    = sy[start & (ND / 4 - 1)];   // constant per thread
    float4* o = (float4*)out + (size_t)b * NT * (ND / 4);
    const size_t n4     = (size_t)NT * (ND / 4);      // 1,052,672
    const size_t stride = (size_t)BGX * 256;          // multiple of 128
#pragma unroll 4
    for (size_t i = start; i < n4; i += stride)
        o[i] = val;
}

// ---------------------------------------------------------------------------
extern "C" void kernel_launch(void* const* d_in, const int* in_sizes, int n_in,
                              void* d_out, int out_size) {
    const float* x     = (const float*)d_in[0];
    const float* pm    = (const float*)d_in[1];
    // d_in[2]=Wk, [3]=bk, [6]=Wq, [7]=bq unused: softmax over zero-state and
    // constant-in-m logits collapse to uniform attention weights.
    const float* Wv    = (const float*)d_in[4];
    const float* bv    = (const float*)d_in[5];
    const float* gamma = (const float*)d_in[8];
    const float* beta  = (const float*)d_in[9];
    const float* Wout  = (const float*)d_in[10];
    const float* bout  = (const float*)d_in[11];

    reduce_x_kernel<<<dim3(NB, ZCH), 128>>>((const float4*)x);
    gemv1_kernel<<<dim3(NB, KZ), ND>>>(pm, Wv);
    gemv2_kernel<<<dim3(NB, KZ), ND>>>(bv, gamma, beta, Wout);
    bcast_kernel<<<dim3(BGX, NB), 256>>>((const float4*)bout, (float*)d_out);
}